// round 1
// baseline (speedup 1.0000x reference)
#include <cuda_runtime.h>
#include <math.h>

// ---------------------------------------------------------------------------
// Problem: SimplifiedIFEBranch
//   inp_img [32,3,512,512] f32, W1[1024,3072], b1[1024], W2[512,1024], b2[512],
//   W3[256,512], b3[256]  ->  out [32,256,1,1] f32
// Pipeline: per-image RGB-uv sqrt-normalized histogram (3x32x32 = 3072 feats),
// then 3x (Linear + ReLU).
// ---------------------------------------------------------------------------

#define NBINS 32

// Constants computed exactly as the reference does (double math, then f32).
__device__ __forceinline__ float c_LO() { return (float)(-3.2 - (6.4 / 256.0) / 2.0); }
__device__ __forceinline__ float c_HI() { return (float)( 3.2 - (6.4 / 256.0) / 2.0); }
__device__ __forceinline__ float c_BW() {
    return (float)(((3.2 - (6.4 / 256.0) / 2.0) - (-3.2 - (6.4 / 256.0) / 2.0)) / 32.0);
}

// Scratch (allocation-free rule: __device__ globals)
__device__ float g_histT[3072 * 32];   // [k=3072][b=32]  (transposed activations)
__device__ float g_x1T[1024 * 32];     // [1024][32]
__device__ float g_x2T[512 * 32];      // [512][32]

__device__ __forceinline__ void hist_add(float* h, float Iu, float Iv, float w) {
    const float LO = c_LO(), HI = c_HI(), BW = c_BW();
    if (Iu >= LO && Iu <= HI && Iv >= LO && Iv <= HI) {
        int iu = (int)floorf((Iu - LO) / BW);
        int iv = (int)floorf((Iv - LO) / BW);
        iu = min(max(iu, 0), NBINS - 1);
        iv = min(max(iv, 0), NBINS - 1);
        atomicAdd(&h[iu * NBINS + iv], w);
    }
}

// One CTA per image. 256 threads.
__global__ void hist_kernel(const float* __restrict__ img, float* __restrict__ histT) {
    __shared__ float sh[3 * 1024];
    __shared__ float ssum[3];
    const int b   = blockIdx.x;
    const int tid = threadIdx.x;

    for (int i = tid; i < 3 * 1024; i += 256) sh[i] = 0.0f;
    if (tid < 3) ssum[tid] = 0.0f;
    __syncthreads();

    const float* base = img + (size_t)b * 3 * 512 * 512;

    for (int p = tid; p < 1024; p += 256) {
        int y = p >> 5, x = p & 31;
        int off = (y * 16) * 512 + (x * 16);            // nearest: floor(i*16)
        float r  = base[off];
        float g  = base[512 * 512 + off];
        float bl = base[2 * 512 * 512 + off];
        bool valid = (r > 0.0f) && (g > 0.0f) && (bl > 0.0f);
        if (!valid) continue;
        float w  = sqrtf(r * r + g * g + bl * bl);
        float lr = logf(r), lg = logf(g), lb = logf(bl);
        // i=0: Iu = l0-l2, Iv = l0-l1
        hist_add(&sh[0 * 1024], lr - lb, lr - lg, w);
        // i=1: Iu = l1-l2, Iv = l1-l0
        hist_add(&sh[1 * 1024], lg - lb, lg - lr, w);
        // i=2: Iu = l2-l1, Iv = l2-l0
        hist_add(&sh[2 * 1024], lb - lg, lb - lr, w);
    }
    __syncthreads();

    // per-channel sums
    for (int c = 0; c < 3; ++c) {
        float s = 0.0f;
        for (int i = tid; i < 1024; i += 256) s += sh[c * 1024 + i];
        #pragma unroll
        for (int o = 16; o > 0; o >>= 1) s += __shfl_down_sync(0xffffffffu, s, o);
        if ((tid & 31) == 0) atomicAdd(&ssum[c], s);
    }
    __syncthreads();

    // sqrt-normalize, write transposed: histT[(c*1024 + bin)*32 + b]
    for (int i = tid; i < 1024; i += 256) {
        #pragma unroll
        for (int c = 0; c < 3; ++c) {
            float v = sh[c * 1024 + i] / ssum[c];
            histT[(c * 1024 + i) * 32 + b] = sqrtf(v);
        }
    }
}

// Warp-per-output-neuron FC. lane = batch (32 batches). A is transposed [K,32].
// W is [N,K] row-major (reads each row exactly once, float4 broadcast).
template <int K, bool RELU, bool TRANS_OUT>
__global__ void fc_kernel(const float* __restrict__ AT, const float* __restrict__ W,
                          const float* __restrict__ bias, float* __restrict__ out,
                          int N, int ldo) {
    int warp = (blockIdx.x * blockDim.x + threadIdx.x) >> 5;
    int lane = threadIdx.x & 31;
    if (warp >= N) return;

    const float* wrow = W + (size_t)warp * K;
    float a0 = 0.f, a1 = 0.f, a2 = 0.f, a3 = 0.f;

    #pragma unroll 4
    for (int k = 0; k < K; k += 4) {
        float4 wv = *reinterpret_cast<const float4*>(wrow + k);
        a0 = fmaf(wv.x, AT[(k + 0) * 32 + lane], a0);
        a1 = fmaf(wv.y, AT[(k + 1) * 32 + lane], a1);
        a2 = fmaf(wv.z, AT[(k + 2) * 32 + lane], a2);
        a3 = fmaf(wv.w, AT[(k + 3) * 32 + lane], a3);
    }
    float acc = (a0 + a1) + (a2 + a3) + bias[warp];
    if (RELU) acc = fmaxf(acc, 0.0f);
    if (TRANS_OUT) out[warp * 32 + lane] = acc;       // [N][32]
    else           out[lane * ldo + warp] = acc;       // [32][N] (final out)
}

extern "C" void kernel_launch(void* const* d_in, const int* in_sizes, int n_in,
                              void* d_out, int out_size) {
    const float* inp = (const float*)d_in[0];
    const float* W1  = (const float*)d_in[1];
    const float* b1  = (const float*)d_in[2];
    const float* W2  = (const float*)d_in[3];
    const float* b2  = (const float*)d_in[4];
    const float* W3  = (const float*)d_in[5];
    const float* b3  = (const float*)d_in[6];
    float* out = (float*)d_out;

    float* histT; cudaGetSymbolAddress((void**)&histT, g_histT);
    float* x1T;   cudaGetSymbolAddress((void**)&x1T,   g_x1T);
    float* x2T;   cudaGetSymbolAddress((void**)&x2T,   g_x2T);

    hist_kernel<<<32, 256>>>(inp, histT);
    // L1: 1024 outputs, K=3072
    fc_kernel<3072, true,  true ><<<1024 / 8, 256>>>(histT, W1, b1, x1T, 1024, 0);
    // L2: 512 outputs, K=1024
    fc_kernel<1024, true,  true ><<<512  / 8, 256>>>(x1T,   W2, b2, x2T, 512, 0);
    // L3: 256 outputs, K=512 -> out [32,256]
    fc_kernel<512,  true,  false><<<256  / 8, 256>>>(x2T,   W3, b3, out, 256, 256);
}

// round 2
// speedup vs baseline: 4.0876x; 4.0876x over previous
#include <cuda_runtime.h>
#include <math.h>

// ---------------------------------------------------------------------------
// SimplifiedIFEBranch: RGB-uv histogram (32 imgs, 3x32x32) + 3-layer ReLU MLP.
// Round 2: fix starvation. K-split FC (CTA per output neuron, 8 warps reduce),
// 4-way split histogram with atomic merge.
// ---------------------------------------------------------------------------

#define NBINS 32

__device__ __forceinline__ float c_LO() { return (float)(-3.2 - (6.4 / 256.0) / 2.0); }
__device__ __forceinline__ float c_HI() { return (float)( 3.2 - (6.4 / 256.0) / 2.0); }
__device__ __forceinline__ float c_BW() {
    return (float)(((3.2 - (6.4 / 256.0) / 2.0) - (-3.2 - (6.4 / 256.0) / 2.0)) / 32.0);
}

// Scratch (__device__ globals; no allocation allowed)
__device__ float g_hist[32 * 3 * 1024];   // raw per-image hist [img][c][1024]
__device__ float g_histT[3072 * 32];      // normalized, transposed [k][b]
__device__ float g_x1T[1024 * 32];
__device__ float g_x2T[512 * 32];

__device__ __forceinline__ void hist_add(float* h, float Iu, float Iv, float w) {
    const float LO = c_LO(), HI = c_HI(), BW = c_BW();
    if (Iu >= LO && Iu <= HI && Iv >= LO && Iv <= HI) {
        int iu = (int)floorf((Iu - LO) / BW);
        int iv = (int)floorf((Iv - LO) / BW);
        iu = min(max(iu, 0), NBINS - 1);
        iv = min(max(iv, 0), NBINS - 1);
        atomicAdd(&h[iu * NBINS + iv], w);
    }
}

// 4 CTAs per image, 256 threads, 1 pixel per thread. Private smem hist,
// sparse atomic merge into g_hist.
__global__ void hist_part_kernel(const float* __restrict__ img, float* __restrict__ gh) {
    __shared__ float sh[3 * 1024];
    const int im   = blockIdx.x >> 2;
    const int part = blockIdx.x & 3;
    const int tid  = threadIdx.x;

    for (int i = tid; i < 3 * 1024; i += 256) sh[i] = 0.0f;
    __syncthreads();

    const int p = part * 256 + tid;           // 0..1023
    const int y = p >> 5, x = p & 31;
    const float* base = img + (size_t)im * 3 * 262144;
    const int off = (y * 16) * 512 + (x * 16);   // nearest: floor(i * 16)

    float r  = base[off];
    float g  = base[262144 + off];
    float bl = base[524288 + off];
    if (r > 0.0f && g > 0.0f && bl > 0.0f) {
        float w  = sqrtf(r * r + g * g + bl * bl);
        float lr = logf(r), lg = logf(g), lb = logf(bl);
        hist_add(&sh[0],        lr - lb, lr - lg, w);
        hist_add(&sh[1024],     lg - lb, lg - lr, w);
        hist_add(&sh[2048],     lb - lg, lb - lr, w);
    }
    __syncthreads();

    float* dst = gh + (size_t)im * 3072;
    for (int i = tid; i < 3072; i += 256) {
        float v = sh[i];
        if (v != 0.0f) atomicAdd(&dst[i], v);
    }
}

// 32 CTAs (one per image): per-channel sum, sqrt-normalize, write transposed.
__global__ void hist_norm_kernel(const float* __restrict__ gh, float* __restrict__ histT) {
    __shared__ float ssum[3];
    const int b   = blockIdx.x;
    const int tid = threadIdx.x;
    const float* src = gh + (size_t)b * 3072;

    if (tid < 3) ssum[tid] = 0.0f;
    __syncthreads();

    for (int c = 0; c < 3; ++c) {
        float s = 0.0f;
        for (int i = tid; i < 1024; i += 256) s += src[c * 1024 + i];
        #pragma unroll
        for (int o = 16; o > 0; o >>= 1) s += __shfl_down_sync(0xffffffffu, s, o);
        if ((tid & 31) == 0) atomicAdd(&ssum[c], s);
    }
    __syncthreads();

    for (int i = tid; i < 1024; i += 256) {
        #pragma unroll
        for (int c = 0; c < 3; ++c) {
            float inv = 1.0f / ssum[c];
            histT[(c * 1024 + i) * 32 + b] = sqrtf(src[c * 1024 + i] * inv);
        }
    }
}

// One CTA per output neuron. 8 warps split K; lane = batch. Smem reduce.
// W row read exactly once; AT [K,32] gives coalesced 128B activation loads.
template <int K, bool RELU, bool TRANS_OUT>
__global__ void fc_kernel(const float* __restrict__ AT, const float* __restrict__ W,
                          const float* __restrict__ bias, float* __restrict__ out,
                          int ldo) {
    __shared__ float red[8][32];
    const int n    = blockIdx.x;
    const int lane = threadIdx.x & 31;
    const int w    = threadIdx.x >> 5;
    constexpr int CH = K / 8;                 // 384 / 128 / 64 — all %4 == 0

    const float* wrow = W + (size_t)n * K + w * CH;
    const float* a    = AT + (size_t)(w * CH) * 32 + lane;

    float a0 = 0.f, a1 = 0.f, a2 = 0.f, a3 = 0.f;
    #pragma unroll 4
    for (int k = 0; k < CH; k += 4) {
        float4 wv = *reinterpret_cast<const float4*>(wrow + k);
        a0 = fmaf(wv.x, a[(k + 0) * 32], a0);
        a1 = fmaf(wv.y, a[(k + 1) * 32], a1);
        a2 = fmaf(wv.z, a[(k + 2) * 32], a2);
        a3 = fmaf(wv.w, a[(k + 3) * 32], a3);
    }
    red[w][lane] = (a0 + a1) + (a2 + a3);
    __syncthreads();

    if (w == 0) {
        float s = ((red[0][lane] + red[1][lane]) + (red[2][lane] + red[3][lane]))
                + ((red[4][lane] + red[5][lane]) + (red[6][lane] + red[7][lane]));
        s += bias[n];
        if (RELU) s = fmaxf(s, 0.0f);
        if (TRANS_OUT) out[n * 32 + lane] = s;       // [N][32]
        else           out[lane * ldo + n] = s;       // [32][N]
    }
}

extern "C" void kernel_launch(void* const* d_in, const int* in_sizes, int n_in,
                              void* d_out, int out_size) {
    const float* inp = (const float*)d_in[0];
    const float* W1  = (const float*)d_in[1];
    const float* b1  = (const float*)d_in[2];
    const float* W2  = (const float*)d_in[3];
    const float* b2  = (const float*)d_in[4];
    const float* W3  = (const float*)d_in[5];
    const float* b3  = (const float*)d_in[6];
    float* out = (float*)d_out;

    float* ghist; cudaGetSymbolAddress((void**)&ghist, g_hist);
    float* histT; cudaGetSymbolAddress((void**)&histT, g_histT);
    float* x1T;   cudaGetSymbolAddress((void**)&x1T,   g_x1T);
    float* x2T;   cudaGetSymbolAddress((void**)&x2T,   g_x2T);

    cudaMemsetAsync(ghist, 0, 32 * 3072 * sizeof(float));
    hist_part_kernel<<<128, 256>>>(inp, ghist);
    hist_norm_kernel<<<32, 256>>>(ghist, histT);
    fc_kernel<3072, true,  true ><<<1024, 256>>>(histT, W1, b1, x1T, 0);
    fc_kernel<1024, true,  true ><<<512,  256>>>(x1T,   W2, b2, x2T, 0);
    fc_kernel<512,  true,  false><<<256,  256>>>(x2T,   W3, b3, out, 256);
}

// round 3
// speedup vs baseline: 5.0205x; 1.2282x over previous
#include <cuda_runtime.h>
#include <math.h>

// ---------------------------------------------------------------------------
// SimplifiedIFEBranch: RGB-uv histogram (32 imgs, 3x32x32) + 3-layer ReLU MLP.
// R3: 512-thread K-split FC (16 warps) + multi-neuron CTAs for fc1 (A reuse),
// single fused histogram kernel (1024 thr/CTA, one CTA per image).
// ---------------------------------------------------------------------------

#define NBINS 32

__device__ __forceinline__ float c_LO() { return (float)(-3.2 - (6.4 / 256.0) / 2.0); }
__device__ __forceinline__ float c_HI() { return (float)( 3.2 - (6.4 / 256.0) / 2.0); }
__device__ __forceinline__ float c_BW() {
    return (float)(((3.2 - (6.4 / 256.0) / 2.0) - (-3.2 - (6.4 / 256.0) / 2.0)) / 32.0);
}

// Scratch (__device__ globals; no allocation allowed)
__device__ float g_histT[3072 * 32];      // normalized, transposed [k][b]
__device__ float g_x1T[1024 * 32];
__device__ float g_x2T[512 * 32];

__device__ __forceinline__ void hist_add(float* h, float Iu, float Iv, float w) {
    const float LO = c_LO(), HI = c_HI(), BW = c_BW();
    if (Iu >= LO && Iu <= HI && Iv >= LO && Iv <= HI) {
        int iu = (int)floorf((Iu - LO) / BW);
        int iv = (int)floorf((Iv - LO) / BW);
        iu = min(max(iu, 0), NBINS - 1);
        iv = min(max(iv, 0), NBINS - 1);
        atomicAdd(&h[iu * NBINS + iv], w);
    }
}

// One CTA per image, 1024 threads, 1 pixel each. Hist + normalize fused.
__global__ __launch_bounds__(1024) void hist_kernel(const float* __restrict__ img,
                                                    float* __restrict__ histT) {
    __shared__ float sh[3 * 1024];
    __shared__ float ssum[3];
    const int b   = blockIdx.x;
    const int tid = threadIdx.x;

    for (int i = tid; i < 3 * 1024; i += 1024) sh[i] = 0.0f;
    if (tid < 3) ssum[tid] = 0.0f;
    __syncthreads();

    const int y = tid >> 5, x = tid & 31;
    const float* base = img + (size_t)b * 3 * 262144;
    const int off = (y * 16) * 512 + (x * 16);        // nearest: floor(i * 16)

    float r  = base[off];
    float g  = base[262144 + off];
    float bl = base[524288 + off];
    if (r > 0.0f && g > 0.0f && bl > 0.0f) {
        float w  = sqrtf(r * r + g * g + bl * bl);
        float lr = logf(r), lg = logf(g), lb = logf(bl);
        hist_add(&sh[0],    lr - lb, lr - lg, w);
        hist_add(&sh[1024], lg - lb, lg - lr, w);
        hist_add(&sh[2048], lb - lg, lb - lr, w);
    }
    __syncthreads();

    // per-channel sums: thread tid owns element tid of each channel
    {
        #pragma unroll
        for (int c = 0; c < 3; ++c) {
            float s = sh[c * 1024 + tid];
            #pragma unroll
            for (int o = 16; o > 0; o >>= 1) s += __shfl_down_sync(0xffffffffu, s, o);
            if ((tid & 31) == 0) atomicAdd(&ssum[c], s);
        }
    }
    __syncthreads();

    // sqrt-normalize, write transposed: histT[(c*1024 + bin)*32 + b]
    {
        const int i = tid;
        #pragma unroll
        for (int c = 0; c < 3; ++c) {
            float v = sh[c * 1024 + i] / ssum[c];
            histT[(c * 1024 + i) * 32 + b] = sqrtf(v);
        }
    }
}

// FC: one CTA per NT output neurons, 16 warps split K, lane = batch.
// W rows broadcast as float4 (1 transaction/warp); AT [K,32] coalesced.
template <int K, int NT, bool RELU, bool TRANS_OUT>
__global__ __launch_bounds__(512) void fc_kernel(const float* __restrict__ AT,
                                                 const float* __restrict__ W,
                                                 const float* __restrict__ bias,
                                                 float* __restrict__ out, int ldo) {
    constexpr int WARPS = 16;
    constexpr int CH = K / WARPS;             // 192 / 64 / 32
    __shared__ float red[WARPS][NT][32];

    const int n0   = blockIdx.x * NT;
    const int lane = threadIdx.x & 31;
    const int w    = threadIdx.x >> 5;

    const float* a = AT + (size_t)(w * CH) * 32 + lane;

    float acc[NT][4];
    #pragma unroll
    for (int t = 0; t < NT; ++t)
        #pragma unroll
        for (int j = 0; j < 4; ++j) acc[t][j] = 0.0f;

    #pragma unroll 4
    for (int k = 0; k < CH; k += 4) {
        float av0 = a[(k + 0) * 32];
        float av1 = a[(k + 1) * 32];
        float av2 = a[(k + 2) * 32];
        float av3 = a[(k + 3) * 32];
        #pragma unroll
        for (int t = 0; t < NT; ++t) {
            float4 wv = *reinterpret_cast<const float4*>(
                W + (size_t)(n0 + t) * K + w * CH + k);
            acc[t][0] = fmaf(wv.x, av0, acc[t][0]);
            acc[t][1] = fmaf(wv.y, av1, acc[t][1]);
            acc[t][2] = fmaf(wv.z, av2, acc[t][2]);
            acc[t][3] = fmaf(wv.w, av3, acc[t][3]);
        }
    }
    #pragma unroll
    for (int t = 0; t < NT; ++t)
        red[w][t][lane] = (acc[t][0] + acc[t][1]) + (acc[t][2] + acc[t][3]);
    __syncthreads();

    if (w < NT) {
        const int t = w;
        float s = 0.0f;
        #pragma unroll
        for (int j = 0; j < WARPS; ++j) s += red[j][t][lane];
        s += bias[n0 + t];
        if (RELU) s = fmaxf(s, 0.0f);
        if (TRANS_OUT) out[(n0 + t) * 32 + lane] = s;     // [N][32]
        else           out[lane * ldo + (n0 + t)] = s;     // [32][N]
    }
}

extern "C" void kernel_launch(void* const* d_in, const int* in_sizes, int n_in,
                              void* d_out, int out_size) {
    const float* inp = (const float*)d_in[0];
    const float* W1  = (const float*)d_in[1];
    const float* b1  = (const float*)d_in[2];
    const float* W2  = (const float*)d_in[3];
    const float* b2  = (const float*)d_in[4];
    const float* W3  = (const float*)d_in[5];
    const float* b3  = (const float*)d_in[6];
    float* out = (float*)d_out;

    float* histT; cudaGetSymbolAddress((void**)&histT, g_histT);
    float* x1T;   cudaGetSymbolAddress((void**)&x1T,   g_x1T);
    float* x2T;   cudaGetSymbolAddress((void**)&x2T,   g_x2T);

    hist_kernel<<<32, 1024>>>(inp, histT);
    // L1: 1024 neurons, K=3072, 2 neurons/CTA (A reuse), grid 512
    fc_kernel<3072, 2, true,  true ><<<512, 512>>>(histT, W1, b1, x1T, 0);
    // L2: 512 neurons, K=1024, grid 512
    fc_kernel<1024, 1, true,  true ><<<512, 512>>>(x1T,   W2, b2, x2T, 0);
    // L3: 256 neurons, K=512, grid 256 -> out [32,256]
    fc_kernel<512,  1, true,  false><<<256, 512>>>(x2T,   W3, b3, out, 256);
}

// round 4
// speedup vs baseline: 5.8809x; 1.1714x over previous
#include <cuda_runtime.h>
#include <math.h>

// ---------------------------------------------------------------------------
// SimplifiedIFEBranch — R4: ONE persistent kernel (128 CTAs x 1024 thr),
// software grid barriers, FFMA2 (fma.rn.f32x2) packed GEMM, L2 prefetch of W1
// overlapped with the histogram phase.
// ---------------------------------------------------------------------------

#define NBINS 32
#define NCTA  128

__device__ __forceinline__ float c_LO() { return (float)(-3.2 - (6.4 / 256.0) / 2.0); }
__device__ __forceinline__ float c_HI() { return (float)( 3.2 - (6.4 / 256.0) / 2.0); }
__device__ __forceinline__ float c_BW() {
    return (float)(((3.2 - (6.4 / 256.0) / 2.0) - (-3.2 - (6.4 / 256.0) / 2.0)) / 32.0);
}

// Scratch + barrier state (__device__ globals; no allocation allowed)
__device__ float g_histT[3072 * 32];      // normalized, transposed [k][b]
__device__ float g_x1T[1024 * 32];
__device__ float g_x2T[512 * 32];
__device__ unsigned int g_bar_count = 0;
__device__ unsigned int g_bar_gen   = 0;

// ---- packed f32x2 helpers --------------------------------------------------
__device__ __forceinline__ unsigned long long pack2(float x, float y) {
    unsigned long long r;
    asm("mov.b64 %0, {%1, %2};" : "=l"(r) : "f"(x), "f"(y));
    return r;
}
__device__ __forceinline__ void ffma2(unsigned long long& d,
                                      unsigned long long a, unsigned long long b) {
    asm("fma.rn.f32x2 %0, %1, %2, %0;" : "+l"(d) : "l"(a), "l"(b));
}
__device__ __forceinline__ float unpack_sum(unsigned long long p) {
    float lo, hi;
    asm("mov.b64 {%0, %1}, %2;" : "=f"(lo), "=f"(hi) : "l"(p));
    return lo + hi;
}

// ---- software grid barrier (all NCTA CTAs resident by construction) --------
__device__ __forceinline__ void grid_barrier() {
    __syncthreads();
    if (threadIdx.x == 0) {
        unsigned gen = *(volatile unsigned*)&g_bar_gen;
        __threadfence();
        unsigned old = atomicAdd(&g_bar_count, 1u);
        if (old == NCTA - 1) {
            g_bar_count = 0;
            __threadfence();
            atomicAdd(&g_bar_gen, 1u);
        } else {
            while (*(volatile unsigned*)&g_bar_gen == gen) { __nanosleep(32); }
        }
        __threadfence();
    }
    __syncthreads();
}

// ---- histogram helpers ------------------------------------------------------
__device__ __forceinline__ void hist_add(float* h, float Iu, float Iv, float w) {
    const float LO = c_LO(), HI = c_HI(), BW = c_BW();
    if (Iu >= LO && Iu <= HI && Iv >= LO && Iv <= HI) {
        int iu = (int)floorf((Iu - LO) / BW);
        int iv = (int)floorf((Iv - LO) / BW);
        iu = min(max(iu, 0), NBINS - 1);
        iv = min(max(iv, 0), NBINS - 1);
        atomicAdd(&h[iu * NBINS + iv], w);
    }
}

// ---- FC phase: 32 warps split K, NT neurons per CTA, lane = batch ----------
// red: [32][NT][32] floats in smem.
template <int K, int NT, bool TRANS_OUT>
__device__ __forceinline__ void fc_phase(const float* __restrict__ AT,
                                         const float* __restrict__ W,
                                         const float* __restrict__ bias,
                                         float* __restrict__ out, int ldo,
                                         float* red) {
    constexpr int CH = K / 32;                     // 96 / 32 / 16
    const int n0   = blockIdx.x * NT;
    const int lane = threadIdx.x & 31;
    const int w    = threadIdx.x >> 5;

    const float* a = AT + (size_t)(w * CH) * 32 + lane;
    const float* wbase = W + (size_t)n0 * K + w * CH;

    unsigned long long acc2[NT];
    #pragma unroll
    for (int t = 0; t < NT; ++t) acc2[t] = 0ull;

    #pragma unroll 4
    for (int k = 0; k < CH; k += 4) {
        float av0 = __ldcg(a + (k + 0) * 32);
        float av1 = __ldcg(a + (k + 1) * 32);
        float av2 = __ldcg(a + (k + 2) * 32);
        float av3 = __ldcg(a + (k + 3) * 32);
        unsigned long long p01 = pack2(av0, av1);
        unsigned long long p23 = pack2(av2, av3);
        #pragma unroll
        for (int t = 0; t < NT; ++t) {
            ulonglong2 wv = __ldcg(reinterpret_cast<const ulonglong2*>(
                wbase + (size_t)t * K + k));
            ffma2(acc2[t], wv.x, p01);
            ffma2(acc2[t], wv.y, p23);
        }
    }
    #pragma unroll
    for (int t = 0; t < NT; ++t)
        red[(w * NT + t) * 32 + lane] = unpack_sum(acc2[t]);
    __syncthreads();

    if (w < NT) {
        const int t = w;
        float s = 0.0f;
        #pragma unroll
        for (int j = 0; j < 32; ++j) s += red[(j * NT + t) * 32 + lane];
        s += __ldcg(bias + n0 + t);
        s = fmaxf(s, 0.0f);
        if (TRANS_OUT) out[(n0 + t) * 32 + lane] = s;   // [N][32]
        else           out[lane * ldo + (n0 + t)] = s;   // [32][N]
    }
    __syncthreads();   // red reused by next phase
}

// ---- the one kernel ---------------------------------------------------------
__global__ __launch_bounds__(1024, 1) void fused_kernel(
    const float* __restrict__ img,
    const float* __restrict__ W1, const float* __restrict__ b1,
    const float* __restrict__ W2, const float* __restrict__ b2,
    const float* __restrict__ W3, const float* __restrict__ b3,
    float* __restrict__ out,
    float* __restrict__ histT, float* __restrict__ x1T, float* __restrict__ x2T) {

    __shared__ float red[32 * 8 * 32];     // 32 KB, reused each fc phase
    __shared__ float sh[3 * 1024];         // hist bins
    __shared__ float ssum[3];

    const int cta = blockIdx.x;
    const int tid = threadIdx.x;

    // ---------------- Phase 0: histogram (CTAs 0..31) + W1 L2 prefetch ------
    if (cta < 32) {
        const int b = cta;
        for (int i = tid; i < 3 * 1024; i += 1024) sh[i] = 0.0f;
        if (tid < 3) ssum[tid] = 0.0f;
        __syncthreads();

        const int y = tid >> 5, x = tid & 31;
        const float* base = img + (size_t)b * 3 * 262144;
        const int off = (y * 16) * 512 + (x * 16);       // nearest: floor(i*16)

        float r  = base[off];
        float g  = base[262144 + off];
        float bl = base[524288 + off];
        if (r > 0.0f && g > 0.0f && bl > 0.0f) {
            float w  = sqrtf(r * r + g * g + bl * bl);
            float lr = logf(r), lg = logf(g), lb = logf(bl);
            hist_add(&sh[0],    lr - lb, lr - lg, w);
            hist_add(&sh[1024], lg - lb, lg - lr, w);
            hist_add(&sh[2048], lb - lg, lb - lr, w);
        }
        __syncthreads();

        #pragma unroll
        for (int c = 0; c < 3; ++c) {
            float s = sh[c * 1024 + tid];
            #pragma unroll
            for (int o = 16; o > 0; o >>= 1) s += __shfl_down_sync(0xffffffffu, s, o);
            if ((tid & 31) == 0) atomicAdd(&ssum[c], s);
        }
        __syncthreads();

        #pragma unroll
        for (int c = 0; c < 3; ++c) {
            float v = sh[c * 1024 + tid] / ssum[c];
            histT[(c * 1024 + tid) * 32 + b] = sqrtf(v);
        }
    } else {
        // 96 CTAs x 1024 thr = 98304 threads, one 128B line each = all of W1
        const int idx = (cta - 32) * 1024 + tid;
        const float* p = W1 + (size_t)idx * 32;
        asm volatile("prefetch.global.L2 [%0];" :: "l"(p));
    }

    grid_barrier();

    // ---------------- Phase 1: fc1  (1024 neurons, K=3072, NT=8) -----------
    fc_phase<3072, 8, true>(histT, W1, b1, x1T, 0, red);
    grid_barrier();

    // ---------------- Phase 2: fc2  (512 neurons, K=1024, NT=4) ------------
    fc_phase<1024, 4, true>(x1T, W2, b2, x2T, 0, red);
    grid_barrier();

    // ---------------- Phase 3: fc3  (256 neurons, K=512, NT=2) -> out ------
    fc_phase<512, 2, false>(x2T, W3, b3, out, 256, red);
}

extern "C" void kernel_launch(void* const* d_in, const int* in_sizes, int n_in,
                              void* d_out, int out_size) {
    const float* inp = (const float*)d_in[0];
    const float* W1  = (const float*)d_in[1];
    const float* b1  = (const float*)d_in[2];
    const float* W2  = (const float*)d_in[3];
    const float* b2  = (const float*)d_in[4];
    const float* W3  = (const float*)d_in[5];
    const float* b3  = (const float*)d_in[6];
    float* out = (float*)d_out;

    float* histT; cudaGetSymbolAddress((void**)&histT, g_histT);
    float* x1T;   cudaGetSymbolAddress((void**)&x1T,   g_x1T);
    float* x2T;   cudaGetSymbolAddress((void**)&x2T,   g_x2T);

    fused_kernel<<<NCTA, 1024>>>(inp, W1, b1, W2, b2, W3, b3, out, histT, x1T, x2T);
}